// round 11
// baseline (speedup 1.0000x reference)
#include <cuda_runtime.h>
#include <cuda_bf16.h>
#include <math.h>
#include <stdint.h>

// Problem constants
#define BATCH   4096
#define HID     1024
#define EMBD    64
#define KDIM    1088          // EMBD + HID
#define NOBS    8
#define NSTEPS  19
#define GROWS   4096          // 4*HID gate rows

// GEMM tiling
#define TM      128           // batch rows per CTA
#define TN      128           // permuted gate cols per CTA = 32 hidden units x 4 gates
#define TKC     64            // K chunk (64 bf16 = 128B rows -> SW128 swizzle)

// smem: 2 stages x 4 tiles (Ahi, Alo, Whi, Wlo) x 16KB = 128KB, + bias
#define STAGE_B 65536
#define T_AHI   0
#define T_ALO   16384
#define T_WHI   32768
#define T_WLO   49152
#define GB_STRIDE 132         // floats per gbuf row (gbuf overlays stage buffers)
#define SBIAS   131072
#define SMEM_BYTES (131072 + 512 + 1024)

// ---------------- device state (allocation-free scratch) ----------------
// X double-buffered by STEP PARITY: gates_kernel(s) reads X[s&1] and writes
// h_{s+1} into X[(s+1)&1] — eliminates the cross-CTA read/write race on h.
__device__ __nv_bfloat16 g_Xhi[2][BATCH * KDIM];  // [emb(64) | h(1024)] hi
__device__ __nv_bfloat16 g_Xlo[2][BATCH * KDIM];  // lo residual
__device__ __nv_bfloat16 g_Wphi[GROWS * KDIM];    // permuted [W_ih|W_hh] hi
__device__ __nv_bfloat16 g_Wplo[GROWS * KDIM];    // lo residual
__device__ float         g_bp[GROWS];             // permuted b_ih+b_hh
__device__ float         g_c[BATCH * HID];        // cell state (fp32)

// ---------------- helpers ----------------
__device__ __forceinline__ uint32_t smem_u32(const void* p) {
    uint32_t a;
    asm("{ .reg .u64 t; cvta.to.shared.u64 t, %1; cvt.u32.u64 %0, t; }" : "=r"(a) : "l"(p));
    return a;
}
__device__ __forceinline__ void cp16(uint32_t dst, const void* src) {
    asm volatile("cp.async.cg.shared.global [%0], [%1], 16;" :: "r"(dst), "l"(src));
}
#define CP_COMMIT() asm volatile("cp.async.commit_group;" ::: "memory")
__device__ __forceinline__ uint32_t swz(uint32_t off) { return off ^ ((off >> 3) & 0x70); }

__device__ __forceinline__ void ldmat4(uint32_t* r, uint32_t addr) {
    asm volatile("ldmatrix.sync.aligned.m8n8.x4.shared.b16 {%0,%1,%2,%3}, [%4];"
        : "=r"(r[0]), "=r"(r[1]), "=r"(r[2]), "=r"(r[3]) : "r"(addr));
}
__device__ __forceinline__ void mma16816(float* c, const uint32_t* a, uint32_t b0, uint32_t b1) {
    asm volatile("mma.sync.aligned.m16n8k16.row.col.f32.bf16.bf16.f32 "
        "{%0,%1,%2,%3}, {%4,%5,%6,%7}, {%8,%9}, {%0,%1,%2,%3};"
        : "+f"(c[0]), "+f"(c[1]), "+f"(c[2]), "+f"(c[3])
        : "r"(a[0]), "r"(a[1]), "r"(a[2]), "r"(a[3]), "r"(b0), "r"(b1));
}

__device__ __forceinline__ float sigf(float x) {
    return __fdividef(1.0f, 1.0f + __expf(-x));
}
__device__ __forceinline__ float tanh_f(float x) {
    return fmaf(2.0f, sigf(2.0f * x), -1.0f);
}

// Load one K-chunk stage: Xhi/Xlo[128x64] + Whi/Wlo[128x64], SW128-swizzled
__device__ __forceinline__ void load_chunk4(uint32_t stage,
                                            const __nv_bfloat16* __restrict__ Xhi,
                                            const __nv_bfloat16* __restrict__ Xlo,
                                            int bm, int bn, int kbase, int tid)
{
    const int r = tid >> 3, q = tid & 7;           // 32 rows x 8 float4-slots per pass
    const size_t arow = (size_t)(bm * TM + r) * KDIM + kbase + q * 8;
    const size_t brow = (size_t)(bn * TN + r) * KDIM + kbase + q * 8;
    #pragma unroll
    for (int u = 0; u < 4; ++u) {                  // 4 x 32 rows = 128 rows
        const uint32_t o = swz((uint32_t)((r + u * 32) * 128 + q * 16));
        const size_t   d = (size_t)u * 32 * KDIM;
        cp16(stage + T_AHI + o, Xhi + arow + d);
        cp16(stage + T_ALO + o, Xlo + arow + d);
        cp16(stage + T_WHI + o, g_Wphi + brow + d);
        cp16(stage + T_WLO + o, g_Wplo + brow + d);
    }
    CP_COMMIT();
}

// ---------------- one-time prep: permute+split W, combine biases ----------------
extern "C" __global__ void __launch_bounds__(256)
prep_kernel(const float* __restrict__ W_ih, const float* __restrict__ b_ih,
            const float* __restrict__ W_hh, const float* __restrict__ b_hh)
{
    int idx = blockIdx.x * 256 + threadIdx.x;       // 0 .. GROWS*KDIM
    int ro = idx / KDIM, k = idx - ro * KDIM;
    int j = ro >> 2, q = ro & 3;                    // ro = j*4 + gate
    int orig = q * HID + j;
    float v = (k < EMBD) ? W_ih[(size_t)orig * EMBD + k]
                         : W_hh[(size_t)orig * HID + (k - EMBD)];
    __nv_bfloat16 hi = __float2bfloat16(v);
    g_Wphi[idx] = hi;
    g_Wplo[idx] = __float2bfloat16(v - __bfloat162float(hi));
    if (k == 0) g_bp[ro] = b_ih[orig] + b_hh[orig];
}

// ---------------- per-step embedding -> X[s&1] cols 0..63 ----------------
extern "C" __global__ void __launch_bounds__(256)
emb_kernel(const float* __restrict__ observed, const float* __restrict__ W_emb,
           const float* __restrict__ b_emb, const float* __restrict__ out, int s)
{
    int idx = blockIdx.x * 256 + threadIdx.x;       // 0 .. BATCH*EMBD
    int row = idx >> 6, e = idx & 63;
    float d0, d1;
    if (s < NOBS) {
        const float* o1 = observed + (size_t)(s + 1) * BATCH * 2 + (size_t)row * 2;
        const float* o0 = observed + (size_t)s       * BATCH * 2 + (size_t)row * 2;
        d0 = o1[0] - o0[0];
        d1 = o1[1] - o0[1];
    } else {
        const float* pv = out + (size_t)(s - 1) * BATCH * 5 + (size_t)row * 5;
        d0 = pv[0];
        d1 = pv[1];
    }
    float v = fmaf(W_emb[e * 2], d0, fmaf(W_emb[e * 2 + 1], d1, b_emb[e]));
    v = fmaxf(v, 0.0f);
    __nv_bfloat16 hi = __float2bfloat16(v);
    g_Xhi[s & 1][(size_t)row * KDIM + e] = hi;
    g_Xlo[s & 1][(size_t)row * KDIM + e] = __float2bfloat16(v - __bfloat162float(hi));
}

// ---------------- fused gates GEMM (mma.sync bf16, chunk-major 3-pass) ----------------
extern "C" __global__ void __launch_bounds__(256, 1)
gates_kernel(int s)
{
    extern __shared__ char smraw[];
    const uint32_t sm0  = smem_u32(smraw);
    const uint32_t base = (sm0 + 1023) & ~1023u;
    const uint32_t pad  = base - sm0;
    const uint32_t Soff[2] = {base, base + STAGE_B};

    const int tid  = threadIdx.x;
    const int wid  = tid >> 5;
    const int lane = tid & 31;
    const int wm   = wid >> 2;      // 0..1 : warp M position (64 rows each)
    const int wn   = wid & 3;       // 0..3 : warp N position (32 cols each)
    const int bn   = blockIdx.x;    // 0..31 (permuted gate-col tile)
    const int bm   = blockIdx.y;    // 0..31 (batch tile)

    const __nv_bfloat16* Xhi_r = g_Xhi[s & 1];
    const __nv_bfloat16* Xlo_r = g_Xlo[s & 1];
    __nv_bfloat16* Xhi_w = g_Xhi[(s + 1) & 1];
    __nv_bfloat16* Xlo_w = g_Xlo[(s + 1) & 1];

    // kick off first chunk ASAP
    load_chunk4(Soff[0], Xhi_r, Xlo_r, bm, bn, 0, tid);

    float* bias_s = (float*)(smraw + pad + SBIAS);
    if (tid < TN) bias_s[tid] = g_bp[bn * TN + tid];

    float acc[4][4][4];
    #pragma unroll
    for (int mt = 0; mt < 4; ++mt)
        #pragma unroll
        for (int nt = 0; nt < 4; ++nt)
            #pragma unroll
            for (int v = 0; v < 4; ++v) acc[mt][nt][v] = 0.0f;

    const int niter = (s == 0) ? 1 : 17;   // step 0: h==0, only emb K-chunk
    const int lrow  = lane & 15;
    const int lhalf = (lane >> 4) * 16;

    for (int it = 0; it < niter; ++it) {
        const int b = it & 1, nb = b ^ 1;
        if (it + 1 < niter) {
            load_chunk4(Soff[nb], Xhi_r, Xlo_r, bm, bn, (it + 1) * TKC, tid);
            asm volatile("cp.async.wait_group 1;" ::: "memory");
        } else {
            asm volatile("cp.async.wait_group 0;" ::: "memory");
        }
        __syncthreads();

        const uint32_t st = Soff[b];
        #pragma unroll
        for (int kk = 0; kk < 4; ++kk) {
            // B fragments (hi and lo), reused by all mt
            uint32_t bhi[2][4], blo[2][4];
            #pragma unroll
            for (int nt2 = 0; nt2 < 2; ++nt2) {
                const uint32_t boff = swz((uint32_t)((wn * 32 + nt2 * 16 + lrow) * 128 + kk * 32 + lhalf));
                ldmat4(bhi[nt2], st + T_WHI + boff);
                ldmat4(blo[nt2], st + T_WLO + boff);
            }
            #pragma unroll
            for (int mt = 0; mt < 4; ++mt) {
                const uint32_t aoff = swz((uint32_t)((wm * 64 + mt * 16 + lrow) * 128 + kk * 32 + lhalf));
                uint32_t ahi[4], alo[4];
                ldmat4(ahi, st + T_AHI + aoff);
                ldmat4(alo, st + T_ALO + aoff);
                #pragma unroll
                for (int nt = 0; nt < 4; ++nt) {
                    const uint32_t* bf = bhi[nt >> 1];
                    uint32_t b0 = (nt & 1) ? bf[1] : bf[0];
                    uint32_t b1 = (nt & 1) ? bf[3] : bf[2];
                    mma16816(acc[mt][nt], ahi, b0, b1);
                    mma16816(acc[mt][nt], alo, b0, b1);
                    const uint32_t* bl = blo[nt >> 1];
                    uint32_t c0 = (nt & 1) ? bl[1] : bl[0];
                    uint32_t c1 = (nt & 1) ? bl[3] : bl[2];
                    mma16816(acc[mt][nt], ahi, c0, c1);
                }
            }
        }
        __syncthreads();
    }

    // ------- dump accumulators to smem (gbuf overlays stage buffers) -------
    float* gbuf = (float*)(smraw + pad);
    #pragma unroll
    for (int mt = 0; mt < 4; ++mt)
        #pragma unroll
        for (int nt = 0; nt < 4; ++nt) {
            int r0 = wm * 64 + mt * 16 + (lane >> 2);
            int c  = wn * 32 + nt * 8 + (lane & 3) * 2;
            *(float2*)&gbuf[r0 * GB_STRIDE + c]       = make_float2(acc[mt][nt][0], acc[mt][nt][1]);
            *(float2*)&gbuf[(r0 + 8) * GB_STRIDE + c] = make_float2(acc[mt][nt][2], acc[mt][nt][3]);
        }
    __syncthreads();

    // ------- fused LSTM cell update: 128 rows x 32 hidden units per CTA -------
    #pragma unroll
    for (int u = 0; u < 16; ++u) {
        int idx = tid + 256 * u;       // 0..4095
        int m = idx >> 5, j = idx & 31;
        int row = bm * TM + m;
        int jglob = bn * 32 + j;
        const float* gp = &gbuf[m * GB_STRIDE + j * 4];
        float gi = gp[0] + bias_s[j * 4 + 0];
        float gf = gp[1] + bias_s[j * 4 + 1];
        float gg = gp[2] + bias_s[j * 4 + 2];
        float go = gp[3] + bias_s[j * 4 + 3];
        float xi = sigf(gi), xf = sigf(gf);
        float xg = tanh_f(gg), xo = sigf(go);
        size_t ci = (size_t)row * HID + jglob;
        float cold = (s > 0) ? g_c[ci] : 0.0f;
        float cn = fmaf(xf, cold, xi * xg);
        g_c[ci] = cn;
        float hn = xo * tanh_f(cn);
        __nv_bfloat16 hb = __float2bfloat16(hn);
        Xhi_w[(size_t)row * KDIM + EMBD + jglob] = hb;
        Xlo_w[(size_t)row * KDIM + EMBD + jglob] =
            __float2bfloat16(hn - __bfloat162float(hb));
    }
}

// ---------------- output projection: out[s] = h @ W_out^T + b_out ----------------
extern "C" __global__ void __launch_bounds__(256)
out_proj_kernel(const float* __restrict__ W_out, const float* __restrict__ b_out,
                float* __restrict__ out, int s)
{
    __shared__ float ws[5 * HID];
    for (int i = threadIdx.x; i < 5 * HID; i += 256) ws[i] = W_out[i];
    __syncthreads();

    int w = threadIdx.x >> 5, lane = threadIdx.x & 31;
    int row = blockIdx.x * 8 + w;
    // h_s was written by gates_kernel(s) into buffer (s+1)&1
    const __nv_bfloat16* xh = g_Xhi[(s + 1) & 1] + (size_t)row * KDIM + EMBD;
    const __nv_bfloat16* xl = g_Xlo[(s + 1) & 1] + (size_t)row * KDIM + EMBD;

    float a0 = 0.f, a1 = 0.f, a2 = 0.f, a3 = 0.f, a4 = 0.f;
    #pragma unroll
    for (int it = 0; it < 4; ++it) {
        int k0 = it * 256 + lane * 8;
        union { uint4 v; __nv_bfloat16 bb[8]; } uh, ul;
        uh.v = *(const uint4*)(xh + k0);
        ul.v = *(const uint4*)(xl + k0);
        #pragma unroll
        for (int t = 0; t < 8; ++t) {
            float a = __bfloat162float(uh.bb[t]) + __bfloat162float(ul.bb[t]);
            int k = k0 + t;
            a0 = fmaf(a, ws[0 * HID + k], a0);
            a1 = fmaf(a, ws[1 * HID + k], a1);
            a2 = fmaf(a, ws[2 * HID + k], a2);
            a3 = fmaf(a, ws[3 * HID + k], a3);
            a4 = fmaf(a, ws[4 * HID + k], a4);
        }
    }
    #pragma unroll
    for (int off = 16; off; off >>= 1) {
        a0 += __shfl_xor_sync(0xffffffff, a0, off);
        a1 += __shfl_xor_sync(0xffffffff, a1, off);
        a2 += __shfl_xor_sync(0xffffffff, a2, off);
        a3 += __shfl_xor_sync(0xffffffff, a3, off);
        a4 += __shfl_xor_sync(0xffffffff, a4, off);
    }
    if (lane == 0) {
        float* o = out + (size_t)s * BATCH * 5 + (size_t)row * 5;
        o[0] = a0 + b_out[0];
        o[1] = a1 + b_out[1];
        o[2] = a2 + b_out[2];
        o[3] = a3 + b_out[3];
        o[4] = a4 + b_out[4];
    }
}

extern "C" void kernel_launch(void* const* d_in, const int* in_sizes, int n_in,
                              void* d_out, int out_size)
{
    const float* observed = (const float*)d_in[0];
    const float* W_emb    = (const float*)d_in[1];
    const float* b_emb    = (const float*)d_in[2];
    const float* W_ih     = (const float*)d_in[3];
    const float* b_ih     = (const float*)d_in[4];
    const float* W_hh     = (const float*)d_in[5];
    const float* b_hh     = (const float*)d_in[6];
    const float* W_out    = (const float*)d_in[7];
    const float* b_out    = (const float*)d_in[8];
    float* out = (float*)d_out;

    cudaFuncSetAttribute(gates_kernel, cudaFuncAttributeMaxDynamicSharedMemorySize, SMEM_BYTES);

    prep_kernel<<<(GROWS * KDIM) / 256, 256>>>(W_ih, b_ih, W_hh, b_hh);

    dim3 grid(GROWS / TN, BATCH / TM);   // (32, 32)
    for (int s = 0; s < NSTEPS; ++s) {
        emb_kernel<<<(BATCH * EMBD) / 256, 256>>>(observed, W_emb, b_emb, out, s);
        gates_kernel<<<grid, 256, SMEM_BYTES>>>(s);
        out_proj_kernel<<<BATCH / 8, 256>>>(W_out, b_out, out, s);
    }
}

// round 12
// speedup vs baseline: 1.0796x; 1.0796x over previous
#include <cuda_runtime.h>
#include <cuda_bf16.h>
#include <math.h>
#include <stdint.h>

// Problem constants
#define BATCH   4096
#define HID     1024
#define EMBD    64
#define KDIM    1088          // EMBD + HID
#define NOBS    8
#define NSTEPS  19
#define GROWS   4096          // 4*HID gate rows

// GEMM tiling
#define TM      128           // batch rows per CTA
#define TN      128           // permuted gate cols per CTA = 32 hidden units x 4 gates
#define TKC     32            // K chunk (32 bf16 = 64B rows -> SW64 swizzle)

// smem: 2 stages x 4 tiles (Ahi, Alo, Whi, Wlo) x 8KB = 64KB, + bias
// gbuf (128 x 132 floats = 67584B) overlays the stage buffers after the GEMM.
#define TILE_B  8192
#define STAGE_B 32768
#define T_AHI   0
#define T_ALO   8192
#define T_WHI   16384
#define T_WLO   24576
#define GB_STRIDE 132
#define SBIAS   67584
#define SMEM_BYTES (67584 + 512 + 1024)

// ---------------- device state (allocation-free scratch) ----------------
// X double-buffered by STEP PARITY: gates_kernel(s) reads X[s&1] and writes
// h_{s+1} into X[(s+1)&1] — eliminates the cross-CTA read/write race on h.
__device__ __nv_bfloat16 g_Xhi[2][BATCH * KDIM];  // [emb(64) | h(1024)] hi
__device__ __nv_bfloat16 g_Xlo[2][BATCH * KDIM];  // lo residual
__device__ __nv_bfloat16 g_Wphi[GROWS * KDIM];    // permuted [W_ih|W_hh] hi
__device__ __nv_bfloat16 g_Wplo[GROWS * KDIM];    // lo residual
__device__ float         g_bp[GROWS];             // permuted b_ih+b_hh
__device__ float         g_c[BATCH * HID];        // cell state (fp32)

// ---------------- helpers ----------------
__device__ __forceinline__ uint32_t smem_u32(const void* p) {
    uint32_t a;
    asm("{ .reg .u64 t; cvta.to.shared.u64 t, %1; cvt.u32.u64 %0, t; }" : "=r"(a) : "l"(p));
    return a;
}
__device__ __forceinline__ void cp16(uint32_t dst, const void* src) {
    asm volatile("cp.async.cg.shared.global [%0], [%1], 16;" :: "r"(dst), "l"(src));
}
#define CP_COMMIT() asm volatile("cp.async.commit_group;" ::: "memory")
// SW64 swizzle for 64-byte rows
__device__ __forceinline__ uint32_t swz64(uint32_t off) { return off ^ ((off >> 3) & 0x30); }

__device__ __forceinline__ void ldmat4(uint32_t* r, uint32_t addr) {
    asm volatile("ldmatrix.sync.aligned.m8n8.x4.shared.b16 {%0,%1,%2,%3}, [%4];"
        : "=r"(r[0]), "=r"(r[1]), "=r"(r[2]), "=r"(r[3]) : "r"(addr));
}
__device__ __forceinline__ void mma16816(float* c, const uint32_t* a, uint32_t b0, uint32_t b1) {
    asm volatile("mma.sync.aligned.m16n8k16.row.col.f32.bf16.bf16.f32 "
        "{%0,%1,%2,%3}, {%4,%5,%6,%7}, {%8,%9}, {%0,%1,%2,%3};"
        : "+f"(c[0]), "+f"(c[1]), "+f"(c[2]), "+f"(c[3])
        : "r"(a[0]), "r"(a[1]), "r"(a[2]), "r"(a[3]), "r"(b0), "r"(b1));
}

__device__ __forceinline__ float sigf(float x) {
    return __fdividef(1.0f, 1.0f + __expf(-x));
}
__device__ __forceinline__ float tanh_f(float x) {
    return fmaf(2.0f, sigf(2.0f * x), -1.0f);
}

// Load one K-chunk stage: Xhi/Xlo[128x32] + Whi/Wlo[128x32] bf16, SW64-swizzled
__device__ __forceinline__ void load_chunk4(uint32_t stage,
                                            const __nv_bfloat16* __restrict__ Xhi,
                                            const __nv_bfloat16* __restrict__ Xlo,
                                            int bm, int bn, int kbase, int tid)
{
    const int r = tid >> 2, q = tid & 3;           // 64 rows x 4 16B-quads per pass
    #pragma unroll
    for (int u = 0; u < 2; ++u) {                  // 2 x 64 rows = 128 rows
        const int row = r + u * 64;
        const uint32_t o = swz64((uint32_t)(row * 64 + q * 16));
        const size_t arow = (size_t)(bm * TM + row) * KDIM + kbase + q * 8;
        const size_t brow = (size_t)(bn * TN + row) * KDIM + kbase + q * 8;
        cp16(stage + T_AHI + o, Xhi + arow);
        cp16(stage + T_ALO + o, Xlo + arow);
        cp16(stage + T_WHI + o, g_Wphi + brow);
        cp16(stage + T_WLO + o, g_Wplo + brow);
    }
    CP_COMMIT();
}

// ---------------- one-time prep: permute+split W, combine biases ----------------
extern "C" __global__ void __launch_bounds__(256)
prep_kernel(const float* __restrict__ W_ih, const float* __restrict__ b_ih,
            const float* __restrict__ W_hh, const float* __restrict__ b_hh)
{
    int idx = blockIdx.x * 256 + threadIdx.x;       // 0 .. GROWS*KDIM
    int ro = idx / KDIM, k = idx - ro * KDIM;
    int j = ro >> 2, q = ro & 3;                    // ro = j*4 + gate
    int orig = q * HID + j;
    float v = (k < EMBD) ? W_ih[(size_t)orig * EMBD + k]
                         : W_hh[(size_t)orig * HID + (k - EMBD)];
    __nv_bfloat16 hi = __float2bfloat16(v);
    g_Wphi[idx] = hi;
    g_Wplo[idx] = __float2bfloat16(v - __bfloat162float(hi));
    if (k == 0) g_bp[ro] = b_ih[orig] + b_hh[orig];
}

// ---------------- per-step embedding -> X[s&1] cols 0..63 ----------------
extern "C" __global__ void __launch_bounds__(256)
emb_kernel(const float* __restrict__ observed, const float* __restrict__ W_emb,
           const float* __restrict__ b_emb, const float* __restrict__ out, int s)
{
    int idx = blockIdx.x * 256 + threadIdx.x;       // 0 .. BATCH*EMBD
    int row = idx >> 6, e = idx & 63;
    float d0, d1;
    if (s < NOBS) {
        const float* o1 = observed + (size_t)(s + 1) * BATCH * 2 + (size_t)row * 2;
        const float* o0 = observed + (size_t)s       * BATCH * 2 + (size_t)row * 2;
        d0 = o1[0] - o0[0];
        d1 = o1[1] - o0[1];
    } else {
        const float* pv = out + (size_t)(s - 1) * BATCH * 5 + (size_t)row * 5;
        d0 = pv[0];
        d1 = pv[1];
    }
    float v = fmaf(W_emb[e * 2], d0, fmaf(W_emb[e * 2 + 1], d1, b_emb[e]));
    v = fmaxf(v, 0.0f);
    __nv_bfloat16 hi = __float2bfloat16(v);
    g_Xhi[s & 1][(size_t)row * KDIM + e] = hi;
    g_Xlo[s & 1][(size_t)row * KDIM + e] = __float2bfloat16(v - __bfloat162float(hi));
}

// ---------------- fused gates GEMM (mma.sync bf16, chunk-major 3-pass) ----------------
extern "C" __global__ void __launch_bounds__(256, 2)
gates_kernel(int s)
{
    extern __shared__ char smraw[];
    const uint32_t sm0  = smem_u32(smraw);
    const uint32_t base = (sm0 + 1023) & ~1023u;
    const uint32_t pad  = base - sm0;
    const uint32_t Soff[2] = {base, base + STAGE_B};

    const int tid  = threadIdx.x;
    const int wid  = tid >> 5;
    const int lane = tid & 31;
    const int wm   = wid >> 2;      // 0..1 : warp M position (64 rows each)
    const int wn   = wid & 3;       // 0..3 : warp N position (32 cols each)
    const int bn   = blockIdx.x;    // 0..31 (permuted gate-col tile)
    const int bm   = blockIdx.y;    // 0..31 (batch tile)

    const __nv_bfloat16* Xhi_r = g_Xhi[s & 1];
    const __nv_bfloat16* Xlo_r = g_Xlo[s & 1];
    __nv_bfloat16* Xhi_w = g_Xhi[(s + 1) & 1];
    __nv_bfloat16* Xlo_w = g_Xlo[(s + 1) & 1];

    // kick off first chunk ASAP
    load_chunk4(Soff[0], Xhi_r, Xlo_r, bm, bn, 0, tid);

    float* bias_s = (float*)(smraw + pad + SBIAS);
    if (tid < TN) bias_s[tid] = g_bp[bn * TN + tid];

    float acc[4][4][4];
    #pragma unroll
    for (int mt = 0; mt < 4; ++mt)
        #pragma unroll
        for (int nt = 0; nt < 4; ++nt)
            #pragma unroll
            for (int v = 0; v < 4; ++v) acc[mt][nt][v] = 0.0f;

    const int niter = (s == 0) ? 2 : 34;   // step 0: h==0, only emb K-chunks
    const int lrow  = lane & 15;
    const int lhalf = (lane >> 4) * 16;

    for (int it = 0; it < niter; ++it) {
        const int b = it & 1, nb = b ^ 1;
        if (it + 1 < niter) {
            load_chunk4(Soff[nb], Xhi_r, Xlo_r, bm, bn, (it + 1) * TKC, tid);
            asm volatile("cp.async.wait_group 1;" ::: "memory");
        } else {
            asm volatile("cp.async.wait_group 0;" ::: "memory");
        }
        __syncthreads();

        const uint32_t st = Soff[b];
        #pragma unroll
        for (int kk = 0; kk < 2; ++kk) {
            // B fragments (hi and lo), reused by all mt
            uint32_t bhi[2][4], blo[2][4];
            #pragma unroll
            for (int nt2 = 0; nt2 < 2; ++nt2) {
                const uint32_t boff = swz64((uint32_t)((wn * 32 + nt2 * 16 + lrow) * 64 + kk * 32 + lhalf));
                ldmat4(bhi[nt2], st + T_WHI + boff);
                ldmat4(blo[nt2], st + T_WLO + boff);
            }
            #pragma unroll
            for (int mt = 0; mt < 4; ++mt) {
                const uint32_t aoff = swz64((uint32_t)((wm * 64 + mt * 16 + lrow) * 64 + kk * 32 + lhalf));
                uint32_t ahi[4], alo[4];
                ldmat4(ahi, st + T_AHI + aoff);
                ldmat4(alo, st + T_ALO + aoff);
                #pragma unroll
                for (int nt = 0; nt < 4; ++nt) {
                    const uint32_t* bf = bhi[nt >> 1];
                    uint32_t b0 = (nt & 1) ? bf[1] : bf[0];
                    uint32_t b1 = (nt & 1) ? bf[3] : bf[2];
                    mma16816(acc[mt][nt], ahi, b0, b1);
                    mma16816(acc[mt][nt], alo, b0, b1);
                    const uint32_t* bl = blo[nt >> 1];
                    uint32_t c0 = (nt & 1) ? bl[1] : bl[0];
                    uint32_t c1 = (nt & 1) ? bl[3] : bl[2];
                    mma16816(acc[mt][nt], ahi, c0, c1);
                }
            }
        }
        __syncthreads();
    }

    // ------- dump accumulators to smem (gbuf overlays stage buffers) -------
    float* gbuf = (float*)(smraw + pad);
    #pragma unroll
    for (int mt = 0; mt < 4; ++mt)
        #pragma unroll
        for (int nt = 0; nt < 4; ++nt) {
            int r0 = wm * 64 + mt * 16 + (lane >> 2);
            int c  = wn * 32 + nt * 8 + (lane & 3) * 2;
            *(float2*)&gbuf[r0 * GB_STRIDE + c]       = make_float2(acc[mt][nt][0], acc[mt][nt][1]);
            *(float2*)&gbuf[(r0 + 8) * GB_STRIDE + c] = make_float2(acc[mt][nt][2], acc[mt][nt][3]);
        }
    __syncthreads();

    // ------- fused LSTM cell update: 128 rows x 32 hidden units per CTA -------
    #pragma unroll
    for (int u = 0; u < 16; ++u) {
        int idx = tid + 256 * u;       // 0..4095
        int m = idx >> 5, j = idx & 31;
        int row = bm * TM + m;
        int jglob = bn * 32 + j;
        const float* gp = &gbuf[m * GB_STRIDE + j * 4];
        float gi = gp[0] + bias_s[j * 4 + 0];
        float gf = gp[1] + bias_s[j * 4 + 1];
        float gg = gp[2] + bias_s[j * 4 + 2];
        float go = gp[3] + bias_s[j * 4 + 3];
        float xi = sigf(gi), xf = sigf(gf);
        float xg = tanh_f(gg), xo = sigf(go);
        size_t ci = (size_t)row * HID + jglob;
        float cold = (s > 0) ? g_c[ci] : 0.0f;
        float cn = fmaf(xf, cold, xi * xg);
        g_c[ci] = cn;
        float hn = xo * tanh_f(cn);
        __nv_bfloat16 hb = __float2bfloat16(hn);
        Xhi_w[(size_t)row * KDIM + EMBD + jglob] = hb;
        Xlo_w[(size_t)row * KDIM + EMBD + jglob] =
            __float2bfloat16(hn - __bfloat162float(hb));
    }
}

// ---------------- output projection: out[s] = h @ W_out^T + b_out ----------------
extern "C" __global__ void __launch_bounds__(256)
out_proj_kernel(const float* __restrict__ W_out, const float* __restrict__ b_out,
                float* __restrict__ out, int s)
{
    __shared__ float ws[5 * HID];
    for (int i = threadIdx.x; i < 5 * HID; i += 256) ws[i] = W_out[i];
    __syncthreads();

    int w = threadIdx.x >> 5, lane = threadIdx.x & 31;
    int row = blockIdx.x * 8 + w;
    // h_s was written by gates_kernel(s) into buffer (s+1)&1
    const __nv_bfloat16* xh = g_Xhi[(s + 1) & 1] + (size_t)row * KDIM + EMBD;
    const __nv_bfloat16* xl = g_Xlo[(s + 1) & 1] + (size_t)row * KDIM + EMBD;

    float a0 = 0.f, a1 = 0.f, a2 = 0.f, a3 = 0.f, a4 = 0.f;
    #pragma unroll
    for (int it = 0; it < 4; ++it) {
        int k0 = it * 256 + lane * 8;
        union { uint4 v; __nv_bfloat16 bb[8]; } uh, ul;
        uh.v = *(const uint4*)(xh + k0);
        ul.v = *(const uint4*)(xl + k0);
        #pragma unroll
        for (int t = 0; t < 8; ++t) {
            float a = __bfloat162float(uh.bb[t]) + __bfloat162float(ul.bb[t]);
            int k = k0 + t;
            a0 = fmaf(a, ws[0 * HID + k], a0);
            a1 = fmaf(a, ws[1 * HID + k], a1);
            a2 = fmaf(a, ws[2 * HID + k], a2);
            a3 = fmaf(a, ws[3 * HID + k], a3);
            a4 = fmaf(a, ws[4 * HID + k], a4);
        }
    }
    #pragma unroll
    for (int off = 16; off; off >>= 1) {
        a0 += __shfl_xor_sync(0xffffffff, a0, off);
        a1 += __shfl_xor_sync(0xffffffff, a1, off);
        a2 += __shfl_xor_sync(0xffffffff, a2, off);
        a3 += __shfl_xor_sync(0xffffffff, a3, off);
        a4 += __shfl_xor_sync(0xffffffff, a4, off);
    }
    if (lane == 0) {
        float* o = out + (size_t)s * BATCH * 5 + (size_t)row * 5;
        o[0] = a0 + b_out[0];
        o[1] = a1 + b_out[1];
        o[2] = a2 + b_out[2];
        o[3] = a3 + b_out[3];
        o[4] = a4 + b_out[4];
    }
}

extern "C" void kernel_launch(void* const* d_in, const int* in_sizes, int n_in,
                              void* d_out, int out_size)
{
    const float* observed = (const float*)d_in[0];
    const float* W_emb    = (const float*)d_in[1];
    const float* b_emb    = (const float*)d_in[2];
    const float* W_ih     = (const float*)d_in[3];
    const float* b_ih     = (const float*)d_in[4];
    const float* W_hh     = (const float*)d_in[5];
    const float* b_hh     = (const float*)d_in[6];
    const float* W_out    = (const float*)d_in[7];
    const float* b_out    = (const float*)d_in[8];
    float* out = (float*)d_out;

    cudaFuncSetAttribute(gates_kernel, cudaFuncAttributeMaxDynamicSharedMemorySize, SMEM_BYTES);

    prep_kernel<<<(GROWS * KDIM) / 256, 256>>>(W_ih, b_ih, W_hh, b_hh);

    dim3 grid(GROWS / TN, BATCH / TM);   // (32, 32)
    for (int s = 0; s < NSTEPS; ++s) {
        emb_kernel<<<(BATCH * EMBD) / 256, 256>>>(observed, W_emb, b_emb, out, s);
        gates_kernel<<<grid, 256, SMEM_BYTES>>>(s);
        out_proj_kernel<<<BATCH / 8, 256>>>(W_out, b_out, out, s);
    }
}